// round 17
// baseline (speedup 1.0000x reference)
#include <cuda_runtime.h>
#include <cuda_fp16.h>
#include <math.h>
#include <stdint.h>

// Problem constants
#define BB 8
#define LL 4096
#define CC 256
#define HH 8
#define DD 32
#define CH 128
#define NC 32          // LL / CH
#define TT (BB*LL)     // 32768 tokens

// ---------------- static device scratch (no allocations allowed) ----------------
__device__ __half g_qkv[(size_t)TT * 768];                // qkv per token (fp16)
__device__ float g_C  [(size_t)BB*HH*NC * DD*DD];         // per-chunk KV contributions
__device__ __half g_A2 [(size_t)TT * CC];                 // fp16 activations / attention out
__device__ __half g_W1h[(size_t)768 * 256];               // qkv weight (fp16)
__device__ __half g_W2h[(size_t)256 * 256];               // proj weight (fp16)
__device__ __half g_qh [(size_t)TT * CC];                 // normalized q hat (fp16)

// =========================== small PTX helpers ===========================
__device__ __forceinline__ uint32_t smem_u32(const void* p) {
    uint32_t a;
    asm("{ .reg .u64 t; cvta.to.shared.u64 t, %1; cvt.u32.u64 %0, t; }" : "=r"(a) : "l"(p));
    return a;
}
__device__ __forceinline__ void cpasync16(uint32_t dst, const void* src) {
    asm volatile("cp.async.cg.shared.global [%0], [%1], 16;" :: "r"(dst), "l"(src));
}
__device__ __forceinline__ void cp_commit() {
    asm volatile("cp.async.commit_group;" ::: "memory");
}
template<int N>
__device__ __forceinline__ void cp_wait() {
    asm volatile("cp.async.wait_group %0;" :: "n"(N) : "memory");
}
__device__ __forceinline__ void ldsm4(uint32_t* r, uint32_t addr) {
    asm volatile("ldmatrix.sync.aligned.m8n8.x4.shared.b16 {%0,%1,%2,%3}, [%4];"
                 : "=r"(r[0]), "=r"(r[1]), "=r"(r[2]), "=r"(r[3]) : "r"(addr));
}
__device__ __forceinline__ void mma_f16(float* c, const uint32_t* a, const uint32_t* b) {
    asm volatile("mma.sync.aligned.m16n8k16.row.col.f32.f16.f16.f32 "
                 "{%0,%1,%2,%3}, {%4,%5,%6,%7}, {%8,%9}, {%0,%1,%2,%3};"
                 : "+f"(c[0]), "+f"(c[1]), "+f"(c[2]), "+f"(c[3])
                 : "r"(a[0]), "r"(a[1]), "r"(a[2]), "r"(a[3]), "r"(b[0]), "r"(b[1]));
}
// xor swizzle of 16B chunk index within a 64B row (4 chunks)
__device__ __forceinline__ int sw_chunk(int r, int c) {
    return c ^ (r & 3) ^ ((r >> 2) & 1);
}
__device__ __forceinline__ uint32_t pack_h2(__half a, __half b) {
    uint32_t lo16 = *(uint16_t*)&a, hi16 = *(uint16_t*)&b;
    return lo16 | (hi16 << 16);
}

// =========================== fused fp16 conversion kernel ===========================
#define CONV_ACT_BLK (TT*64/256)      // 8192
#define CONV_W1_BLK  (768*64/256)     // 192
#define CONV_GRID    (CONV_ACT_BLK + CONV_W1_BLK + 256*64/256)

__global__ void conv_all_kernel(const float* __restrict__ x, const float* __restrict__ rp,
                                const float* __restrict__ W1, const float* __restrict__ W2,
                                __half* __restrict__ A2,
                                __half* __restrict__ W1h, __half* __restrict__ W2h)
{
    int blk = blockIdx.x;
    if (blk < CONV_ACT_BLK) {
        int idx = blk * 256 + threadIdx.x;
        int m = idx >> 6, c4 = (idx & 63) << 2;
        float4 h = *(const float4*)&x[(size_t)m * 256 + c4];
        float4 r = *(const float4*)&rp[(size_t)(m & (LL-1)) * 256 + c4];
        h.x += r.x; h.y += r.y; h.z += r.z; h.w += r.w;
        *(uint2*)&A2[(size_t)m * CC + c4] = make_uint2(
            pack_h2(__float2half_rn(h.x), __float2half_rn(h.y)),
            pack_h2(__float2half_rn(h.z), __float2half_rn(h.w)));
    } else {
        const float* W; __half* Wh; int idx;
        if (blk < CONV_ACT_BLK + CONV_W1_BLK) {
            W = W1; Wh = W1h; idx = (blk - CONV_ACT_BLK) * 256 + threadIdx.x;
        } else {
            W = W2; Wh = W2h; idx = (blk - CONV_ACT_BLK - CONV_W1_BLK) * 256 + threadIdx.x;
        }
        int n = idx >> 6, c4 = (idx & 63) << 2;
        float4 h = *(const float4*)&W[(size_t)n * 256 + c4];
        *(uint2*)&Wh[(size_t)n * 256 + c4] = make_uint2(
            pack_h2(__float2half_rn(h.x), __float2half_rn(h.y)),
            pack_h2(__float2half_rn(h.z), __float2half_rn(h.w)));
    }
}

// =========================== HMMA fp16 GEMM: C = A @ W^T (+bias) ===========================
// Pure fp16, K=256, BK=32 slabs (8 total). 3-stage cp.async ring, one sync per slab.
#define NSTG 8

template<bool BIAS, bool OUT16>
__global__ void __launch_bounds__(256, 2) gemm_f16_hmma(
    const __half* __restrict__ A,
    const __half* __restrict__ Bw,
    const float* __restrict__ bias,
    void* __restrict__ Cout, int Ntot)
{
    __shared__ __align__(16) __half As[3][128][32];
    __shared__ __align__(16) __half Bs[3][128][32];
    const uint32_t as_base = smem_u32(As);
    const uint32_t bs_base = smem_u32(Bs);

    const int tid = threadIdx.x;
    const int wid = tid >> 5, lane = tid & 31;
    const int warp_m = wid & 1, warp_n = wid >> 1;
    const int m0 = blockIdx.y * 128;
    const int n0 = blockIdx.x * 128;

    float acc[4][4][4];
#pragma unroll
    for (int mt = 0; mt < 4; mt++)
#pragma unroll
        for (int nt = 0; nt < 4; nt++)
#pragma unroll
            for (int e = 0; e < 4; e++) acc[mt][nt][e] = 0.f;

    const int lr = tid >> 2;
    const int lc = tid & 3;

    auto load_stage = [&](int s, int b) {
#pragma unroll
        for (int l = 0; l < 2; l++) {
            int r = lr + l * 64;
            int ch = sw_chunk(r, lc);
            cpasync16(as_base + (b * 128 + r) * 64 + ch * 16,
                      A  + (size_t)(m0 + r) * 256 + s * 32 + lc * 8);
            cpasync16(bs_base + (b * 128 + r) * 64 + ch * 16,
                      Bw + (size_t)(n0 + r) * 256 + s * 32 + lc * 8);
        }
        cp_commit();
    };

    load_stage(0, 0);
    load_stage(1, 1);

    int b = 0;
    for (int i = 0; i < NSTG; i++) {
        if (i + 1 < NSTG) cp_wait<1>(); else cp_wait<0>();
        __syncthreads();

#pragma unroll
        for (int kk = 0; kk < 2; kk++) {
            uint32_t af[4][4];
#pragma unroll
            for (int mt = 0; mt < 4; mt++) {
                int row = warp_m * 64 + mt * 16 + (lane & 15);
                int ch = sw_chunk(row, kk * 2 + (lane >> 4));
                ldsm4(af[mt], as_base + (b * 128 + row) * 64 + ch * 16);
            }
            uint32_t bf[2][4];
#pragma unroll
            for (int nt2 = 0; nt2 < 2; nt2++) {
                int g = lane >> 3, l8 = lane & 7;
                int row = warp_n * 32 + nt2 * 16 + (g >> 1) * 8 + l8;
                int ch = sw_chunk(row, kk * 2 + (g & 1));
                ldsm4(bf[nt2], bs_base + (b * 128 + row) * 64 + ch * 16);
            }
#pragma unroll
            for (int mt = 0; mt < 4; mt++)
#pragma unroll
                for (int nt = 0; nt < 4; nt++)
                    mma_f16(acc[mt][nt], af[mt], &bf[nt >> 1][(nt & 1) * 2]);
        }

        if (i + 2 < NSTG) {
            int b2 = b + 2; if (b2 >= 3) b2 -= 3;
            load_stage(i + 2, b2);
        }
        if (++b == 3) b = 0;
    }

#pragma unroll
    for (int mt = 0; mt < 4; mt++) {
        int row = m0 + warp_m * 64 + mt * 16 + (lane >> 2);
#pragma unroll
        for (int nt = 0; nt < 4; nt++) {
            int col = n0 + warp_n * 32 + nt * 8 + (lane & 3) * 2;
            float2 v0 = make_float2(acc[mt][nt][0], acc[mt][nt][1]);
            float2 v1 = make_float2(acc[mt][nt][2], acc[mt][nt][3]);
            if (BIAS) {
                float2 bv = *(const float2*)&bias[col];
                v0.x += bv.x; v0.y += bv.y;
                v1.x += bv.x; v1.y += bv.y;
            }
            if (OUT16) {
                __half* Ch = (__half*)Cout;
                *(uint32_t*)&Ch[(size_t)row * Ntot + col] =
                    pack_h2(__float2half_rn(v0.x), __float2half_rn(v0.y));
                *(uint32_t*)&Ch[(size_t)(row + 8) * Ntot + col] =
                    pack_h2(__float2half_rn(v1.x), __float2half_rn(v1.y));
            } else {
                float* Cf = (float*)Cout;
                *(float2*)&Cf[(size_t)row * Ntot + col]       = v0;
                *(float2*)&Cf[(size_t)(row + 8) * Ntot + col] = v1;
            }
        }
    }
}

// ======================= HMMA attention: intra + per-chunk KV contribution =======================
// smem layout (bytes); total 84 KB -> 2 CTAs/SM
#define AT_ED   0                     // 129 floats
#define AT_NQ   640
#define AT_NK   1152
#define AT_QHI  2048
#define AT_QLO  (AT_QHI  + 8192)      // unused (layout stability)
#define AT_KHI  (AT_QLO  + 8192)
#define AT_KTHI (AT_KHI  + 8192)
#define AT_KTLO (AT_KTHI + 8192)      // unused
#define AT_VTHI (AT_KTLO + 8192)
#define AT_SC0H (AT_VTHI + 8192)      // 128 rows x 128 B
#define AT_SC0L (AT_SC0H + 16384)     // scratch
#define AT_SMEM (AT_SC0L + 16384)     // 83968 bytes
// aliases (regions dead by the time they're reused)
#define AT_SC1H AT_QHI                // 64 rows x 128 B
#define AT_CRED AT_SC0H               // 16 KB: 4 warps x 4 KB (sc0 dead after P4)

__global__ void __launch_bounds__(256, 2) attn_chunk_hmma(
    const float* __restrict__ qg, const float* __restrict__ kg,
    __half* __restrict__ qhout, __half* __restrict__ oout)
{
    extern __shared__ char sm[];
    float* ed = (float*)(sm + AT_ED);
    float* nq = (float*)(sm + AT_NQ);
    float* nk = (float*)(sm + AT_NK);
    const uint32_t sb = smem_u32(sm);

    const int n = blockIdx.x, h = blockIdx.y, b = blockIdx.z;
    const int tid = threadIdx.x, lane = tid & 31, wid = tid >> 5;
    const float s = exp2f(-(float)(h + 1));
    for (int i = tid; i <= CH; i += 256) ed[i] = expf(-s * (float)i);

    const size_t tok0 = (size_t)(b*LL + n*CH);
    const size_t base = tok0 * 768 + h*DD;
    const int c4 = (tid & 7) * 4;

    // ---- P1: load q,k,v (fp16); keep q,k in registers across norm barrier ----
    float qsv[4][4], ksv[4][4];
    float sq[4], sk[4];
#pragma unroll
    for (int l = 0; l < 4; l++) {
        int r = (tid >> 3) + l * 32;
        const __half* rowp = &g_qkv[base + (size_t)r * 768 + c4];
        __half hq[4], hk[4], hv4[4];
        *(uint2*)hq  = *(const uint2*)(rowp);
        *(uint2*)hk  = *(const uint2*)(rowp + 256);
        *(uint2*)hv4 = *(const uint2*)(rowp + 512);
        float s1 = 0.f, s2 = 0.f;
#pragma unroll
        for (int j = 0; j < 4; j++) {
            float a = __half2float(hq[j]);
            float c = __half2float(hk[j]);
            qsv[l][j] = a; ksv[l][j] = c;
            s1 += a*a; s2 += c*c;
            int d = c4 + j;
            int aT = d*256 + (((r >> 3) ^ (d & 7)) * 16) + ((r & 7) * 2);
            *(__half*)(sm + AT_VTHI + aT) = hv4[j];
        }
        sq[l] = s1; sk[l] = s2;
    }
#pragma unroll
    for (int m = 1; m < 8; m <<= 1) {
#pragma unroll
        for (int l = 0; l < 4; l++) {
            sq[l] += __shfl_xor_sync(0xffffffffu, sq[l], m);
            sk[l] += __shfl_xor_sync(0xffffffffu, sk[l], m);
        }
    }
    if ((tid & 7) == 0) {
        const float sqD = 5.656854249492380f;
#pragma unroll
        for (int l = 0; l < 4; l++) {
            int r = (tid >> 3) + l * 32;
            nq[r] = (sq[l] > 1e-24f) ? sqD * rsqrtf(sq[l]) : sqD * 1e12f;
            nk[r] = (sk[l] > 1e-24f) ? sqD * rsqrtf(sk[l]) : sqD * 1e12f;
        }
    }
    __syncthreads();

    // ---- P2: normalize + convert from registers ----
    float gq[4], gk[4];
#pragma unroll
    for (int j = 0; j < 4; j++) {
        gq[j] = __ldg(&qg[h*DD + c4 + j]);
        gk[j] = __ldg(&kg[h*DD + c4 + j]);
    }
#pragma unroll
    for (int l = 0; l < 4; l++) {
        int r = (tid >> 3) + l * 32;
        float rq = nq[r], rk = nk[r], dk = ed[CH - r];
        __half qh4[4], kh4[4];
#pragma unroll
        for (int j = 0; j < 4; j++) {
            int d = c4 + j;
            float qn = qsv[l][j] * rq * gq[j];
            float kn = ksv[l][j] * rk * gk[j];
            qh4[j] = __float2half_rn(qn);
            kh4[j] = __float2half_rn(kn);
            __half kth = __float2half_rn(kn * dk);
            int aT = d*256 + (((r >> 3) ^ (d & 7)) * 16) + ((r & 7) * 2);
            *(__half*)(sm + AT_KTHI + aT) = kth;
        }
        int a64 = r*64 + sw_chunk(r, c4 >> 3) * 16 + ((c4 & 7) * 2);
        *(uint2*)(sm + AT_QHI + a64) = *(uint2*)qh4;
        *(uint2*)(sm + AT_KHI + a64) = *(uint2*)kh4;
        *(uint2*)(qhout + (tok0 + r)*CC + h*DD + c4) = *(uint2*)qh4;
    }
    __syncthreads();

    const int g = lane >> 3, l8 = lane & 7;

    // ---- P3: scores half0  S[:, 0:64]  (all 128 rows) ----
    float acc0[8][4];
#pragma unroll
    for (int nt = 0; nt < 8; nt++)
#pragma unroll
        for (int e = 0; e < 4; e++) acc0[nt][e] = 0.f;
#pragma unroll
    for (int kk = 0; kk < 2; kk++) {
        uint32_t af[4];
        int row = wid * 16 + (lane & 15);
        ldsm4(af, sb + AT_QHI + row * 64 + sw_chunk(row, kk * 2 + (lane >> 4)) * 16);
        uint32_t bf[4][4];
#pragma unroll
        for (int nt2 = 0; nt2 < 4; nt2++) {
            int row2 = nt2 * 16 + (g >> 1) * 8 + l8;
            ldsm4(bf[nt2], sb + AT_KHI + row2 * 64 + sw_chunk(row2, kk * 2 + (g & 1)) * 16);
        }
#pragma unroll
        for (int nt = 0; nt < 8; nt++)
            mma_f16(acc0[nt], af, &bf[nt >> 1][(nt & 1) * 2]);
    }
    // mask + decay + write sc0
    {
        int c_lo = wid * 16 + (lane >> 2);
#pragma unroll
        for (int nt = 0; nt < 8; nt++) {
            int mm = nt * 8 + (lane & 3) * 2;
#pragma unroll
            for (int half = 0; half < 2; half++) {
                int c = c_lo + half * 8;
                float v0 = acc0[nt][half*2+0], v1 = acc0[nt][half*2+1];
                int d0 = c - mm, d1 = c - mm - 1;
                float s0 = (d0 >= 0) ? v0 * ed[d0] : 0.f;
                float s1 = (d1 >= 0) ? v1 * ed[d1] : 0.f;
                int addr = c * 128 + (((mm >> 3) ^ (c & 7)) * 16) + ((mm * 2) & 15);
                *(uint32_t*)(sm + AT_SC0H + addr) =
                    pack_h2(__float2half_rn(s0), __float2half_rn(s1));
            }
        }
    }
    __syncthreads();

    // ---- P4: o_intra part A (K = 0..64, all rows) ----
    float oacc[4][4];
#pragma unroll
    for (int nt = 0; nt < 4; nt++)
#pragma unroll
        for (int e = 0; e < 4; e++) oacc[nt][e] = 0.f;
    {
        const int r0 = wid * 16;
#pragma unroll
        for (int kk = 0; kk < 4; kk++) {
            uint32_t af[4];
            int row = r0 + (lane & 15);
            int ch = (kk * 2 + (lane >> 4)) ^ (row & 7);
            ldsm4(af, sb + AT_SC0H + row * 128 + ch * 16);
            uint32_t bf[2][4];
#pragma unroll
            for (int nt2 = 0; nt2 < 2; nt2++) {
                int row2 = nt2 * 16 + (g >> 1) * 8 + l8;
                int ch2 = (kk * 2 + (g & 1)) ^ (row2 & 7);
                ldsm4(bf[nt2], sb + AT_VTHI + row2 * 256 + ch2 * 16);
            }
#pragma unroll
            for (int nt = 0; nt < 4; nt++)
                mma_f16(oacc[nt], af, &bf[nt >> 1][(nt & 1) * 2]);
        }
    }
    // rows 0..63 complete -> write o_intra (fp16) to A2
    if (wid < 4) {
        int c = wid * 16 + (lane >> 2);
#pragma unroll
        for (int nt = 0; nt < 4; nt++) {
            int e = nt * 8 + (lane & 3) * 2;
            size_t go = (tok0 + c) * CC + h*DD + e;
            *(uint32_t*)&oout[go] =
                pack_h2(__float2half_rn(oacc[nt][0]), __float2half_rn(oacc[nt][1]));
            *(uint32_t*)&oout[go + 8*CC] =
                pack_h2(__float2half_rn(oacc[nt][2]), __float2half_rn(oacc[nt][3]));
        }
    }

    // ---- P5: scores half1  S[64:128, 64:128]  (all 8 warps) ----
    float acc1[4][4];
#pragma unroll
    for (int nt = 0; nt < 4; nt++)
#pragma unroll
        for (int e = 0; e < 4; e++) acc1[nt][e] = 0.f;
    const int c0s = 64 + (wid & 3) * 16;
    const int mbs = 64 + (wid >> 2) * 32;
#pragma unroll
    for (int kk = 0; kk < 2; kk++) {
        uint32_t af[4];
        int row = c0s + (lane & 15);
        ldsm4(af, sb + AT_QHI + row * 64 + sw_chunk(row, kk * 2 + (lane >> 4)) * 16);
        uint32_t bf[2][4];
#pragma unroll
        for (int nt2 = 0; nt2 < 2; nt2++) {
            int row2 = mbs + nt2 * 16 + (g >> 1) * 8 + l8;
            ldsm4(bf[nt2], sb + AT_KHI + row2 * 64 + sw_chunk(row2, kk * 2 + (g & 1)) * 16);
        }
#pragma unroll
        for (int nt = 0; nt < 4; nt++)
            mma_f16(acc1[nt], af, &bf[nt >> 1][(nt & 1) * 2]);
    }
    __syncthreads();   // all Q/K fragment reads done; QHI becomes sc1

    {
        int c_lo = c0s + (lane >> 2);
#pragma unroll
        for (int nt = 0; nt < 4; nt++) {
            int mm = mbs + nt * 8 + (lane & 3) * 2;
#pragma unroll
            for (int half = 0; half < 2; half++) {
                int c = c_lo + half * 8;
                float v0 = acc1[nt][half*2+0], v1 = acc1[nt][half*2+1];
                int d0 = c - mm, d1 = c - mm - 1;
                float s0 = (d0 >= 0) ? v0 * ed[d0] : 0.f;
                float s1 = (d1 >= 0) ? v1 * ed[d1] : 0.f;
                int cr = c - 64, mr = mm - 64;
                int addr = cr * 128 + (((mr >> 3) ^ (cr & 7)) * 16) + ((mr * 2) & 15);
                *(uint32_t*)(sm + AT_SC1H + addr) =
                    pack_h2(__float2half_rn(s0), __float2half_rn(s1));
            }
        }
    }
    __syncthreads();

    // ---- P6: warps 4-7: o_intra part B; warps 0-3: C_n ----
    if (wid >= 4) {
        const int r0 = (wid - 4) * 16;
#pragma unroll
        for (int kk = 0; kk < 4; kk++) {
            uint32_t af[4];
            int row = r0 + (lane & 15);
            int ch = (kk * 2 + (lane >> 4)) ^ (row & 7);
            ldsm4(af, sb + AT_SC1H + row * 128 + ch * 16);
            uint32_t bf[2][4];
#pragma unroll
            for (int nt2 = 0; nt2 < 2; nt2++) {
                int row2 = nt2 * 16 + (g >> 1) * 8 + l8;
                int ch2 = ((kk + 4) * 2 + (g & 1)) ^ (row2 & 7);
                ldsm4(bf[nt2], sb + AT_VTHI + row2 * 256 + ch2 * 16);
            }
#pragma unroll
            for (int nt = 0; nt < 4; nt++)
                mma_f16(oacc[nt], af, &bf[nt >> 1][(nt & 1) * 2]);
        }
        int c = wid * 16 + (lane >> 2);
#pragma unroll
        for (int nt = 0; nt < 4; nt++) {
            int e = nt * 8 + (lane & 3) * 2;
            size_t go = (tok0 + c) * CC + h*DD + e;
            *(uint32_t*)&oout[go] =
                pack_h2(__float2half_rn(oacc[nt][0]), __float2half_rn(oacc[nt][1]));
            *(uint32_t*)&oout[go + 8*CC] =
                pack_h2(__float2half_rn(oacc[nt][2]), __float2half_rn(oacc[nt][3]));
        }
    } else {
        float cacc[2][4][4];
#pragma unroll
        for (int mt = 0; mt < 2; mt++)
#pragma unroll
            for (int nt = 0; nt < 4; nt++)
#pragma unroll
                for (int e = 0; e < 4; e++) cacc[mt][nt][e] = 0.f;

#pragma unroll
        for (int kl = 0; kl < 2; kl++) {
            int kk = wid * 2 + kl;
            uint32_t af[2][4];
#pragma unroll
            for (int mt = 0; mt < 2; mt++) {
                int row = mt * 16 + (lane & 15);
                int ch = (kk * 2 + (lane >> 4)) ^ (row & 7);
                ldsm4(af[mt], sb + AT_KTHI + row * 256 + ch * 16);
            }
            uint32_t bf[2][4];
#pragma unroll
            for (int nt2 = 0; nt2 < 2; nt2++) {
                int row2 = nt2 * 16 + (g >> 1) * 8 + l8;
                int ch2 = (kk * 2 + (g & 1)) ^ (row2 & 7);
                ldsm4(bf[nt2], sb + AT_VTHI + row2 * 256 + ch2 * 16);
            }
#pragma unroll
            for (int mt = 0; mt < 2; mt++)
#pragma unroll
                for (int nt = 0; nt < 4; nt++)
                    mma_f16(cacc[mt][nt], af[mt], &bf[nt >> 1][(nt & 1) * 2]);
        }
        float* red = (float*)(sm + AT_CRED) + wid * 1024;
#pragma unroll
        for (int mt = 0; mt < 2; mt++) {
            int d = mt * 16 + (lane >> 2);
#pragma unroll
            for (int nt = 0; nt < 4; nt++) {
                int e = nt * 8 + (lane & 3) * 2;
                *(float2*)&red[d * 32 + e]       = make_float2(cacc[mt][nt][0], cacc[mt][nt][1]);
                *(float2*)&red[(d + 8) * 32 + e] = make_float2(cacc[mt][nt][2], cacc[mt][nt][3]);
            }
        }
    }
    __syncthreads();
    {
        const float* red = (const float*)(sm + AT_CRED);
        const size_t cb = ((size_t)((b*HH + h)*NC + n)) * 1024;
        for (int i = tid; i < 1024; i += 256)
            g_C[cb + i] = red[i] + red[1024 + i] + red[2048 + i] + red[3072 + i];
    }
}

// ======================= fused KV scan + inter-chunk HMMA (one block per (b,h)) =======================
// smem: Q double buffer (2x8KB), KVHI (2KB), C double buffer (2x4KB), ed (1KB)
#define SI_Q0   0
#define SI_Q1   8192
#define SI_KV   16384
#define SI_C0   18432
#define SI_C1   22528
#define SI_ED   26624
#define SI_SMEM (SI_ED + 1024)

__global__ void __launch_bounds__(256) scan_inter_hmma(
    const __half* __restrict__ qh, __half* __restrict__ A2)
{
    __shared__ __align__(16) char sm[SI_SMEM];
    float* ed = (float*)(sm + SI_ED);
    const uint32_t sb = smem_u32(sm);

    const int h = blockIdx.x, b = blockIdx.y;
    const int tid = threadIdx.x, lane = tid & 31, wid = tid >> 5;
    const float s = exp2f(-(float)(h + 1));
    for (int i = tid; i <= CH; i += 256) ed[i] = expf(-s * (float)i);
    const float bd = expf(-s * (float)CH);

    const size_t cbase = ((size_t)(b*HH + h)) * NC * 1024;
    const size_t bt0 = (size_t)b * LL;

    // KV state layout: index i = d*32 + e; thread holds i = tid*4 .. tid*4+3
    const int kv_d = tid >> 3;
    const int kv_e0 = (tid & 7) * 4;

    // preload C_0
    cpasync16(sb + SI_C0 + tid * 16, &g_C[cbase + tid * 4]);
    cp_commit();
    cp_wait<0>();
    __syncthreads();

    float kv[4];
    {
        float4 c0 = *(const float4*)((const float*)(sm + SI_C0) + tid * 4);
        kv[0] = c0.x; kv[1] = c0.y; kv[2] = c0.z; kv[3] = c0.w;   // kv_1
    }

    // issue C_1 and Q_1
    cpasync16(sb + SI_C1 + tid * 16, &g_C[cbase + 1024 + tid * 4]);
    {
        const size_t tokq = bt0 + 1 * CH;
#pragma unroll
        for (int l = 0; l < 2; l++) {
            int i = tid + l * 256;
            int r = i >> 2, c = i & 3;
            cpasync16(sb + SI_Q0 + r * 64 + sw_chunk(r, c) * 16,
                      qh + (tokq + r) * CC + h * DD + c * 8);
        }
    }
    cp_commit();

    const int g = lane >> 3, l8 = lane & 7;

    for (int n = 1; n < NC; n++) {
        cp_wait<0>();
        __syncthreads();

        // write kv state -> KVHI (fp16, swizzled; rows = e, cols = d)
#pragma unroll
        for (int j = 0; j < 4; j++) {
            int e = kv_e0 + j;
            int a = e * 64 + sw_chunk(e, kv_d >> 3) * 16 + (kv_d & 7) * 2;
            *(__half*)(sm + SI_KV + a) = __float2half_rn(kv[j]);
        }
        __syncthreads();

        // MMA: o_inter = q̂_chunk_n @ kv  (128 x 32 x 32)
        const uint32_t qbuf = sb + ((n & 1) ? SI_Q0 : SI_Q1);
        float acc[4][4];
#pragma unroll
        for (int nt = 0; nt < 4; nt++)
#pragma unroll
            for (int e = 0; e < 4; e++) acc[nt][e] = 0.f;

        const int r0 = wid * 16;
#pragma unroll
        for (int kk = 0; kk < 2; kk++) {
            uint32_t af[4];
            int row = r0 + (lane & 15);
            ldsm4(af, qbuf + row * 64 + sw_chunk(row, kk * 2 + (lane >> 4)) * 16);
            uint32_t bf[2][4];
#pragma unroll
            for (int nt2 = 0; nt2 < 2; nt2++) {
                int row2 = nt2 * 16 + (g >> 1) * 8 + l8;
                ldsm4(bf[nt2], sb + SI_KV + row2 * 64 + sw_chunk(row2, kk * 2 + (g & 1)) * 16);
            }
#pragma unroll
            for (int nt = 0; nt < 4; nt++)
                mma_f16(acc[nt], af, &bf[nt >> 1][(nt & 1) * 2]);
        }

        // RMW A2 with decay
        const size_t tok0 = bt0 + (size_t)n * CH;
        int c = r0 + (lane >> 2);
        float a0 = ed[c], a1 = ed[c + 8];
#pragma unroll
        for (int nt = 0; nt < 4; nt++) {
            int e = nt * 8 + (lane & 3) * 2;
#pragma unroll
            for (int half = 0; half < 2; half++) {
                int cc2 = c + half * 8;
                float al = half ? a1 : a0;
                size_t go = (tok0 + cc2) * CC + h*DD + e;
                uint32_t prev = *(uint32_t*)&A2[go];
                __half2 ph = *(__half2*)&prev;
                float ox = __half2float(__low2half(ph))  + al * acc[nt][half*2+0];
                float oy = __half2float(__high2half(ph)) + al * acc[nt][half*2+1];
                *(uint32_t*)&A2[go] =
                    pack_h2(__float2half_rn(ox), __float2half_rn(oy));
            }
        }

        // fold in C_n: kv_{n+1} = bd*kv_n + C_n
        {
            const float* cs = (const float*)(sm + ((n & 1) ? SI_C1 : SI_C0));
            float4 cn = *(const float4*)(cs + tid * 4);
            kv[0] = bd * kv[0] + cn.x;
            kv[1] = bd * kv[1] + cn.y;
            kv[2] = bd * kv[2] + cn.z;
            kv[3] = bd * kv[3] + cn.w;
        }

        // prefetch next C and Q
        if (n + 1 < NC) {
            cpasync16(sb + ((n + 1) & 1 ? SI_C1 : SI_C0) + tid * 16,
                      &g_C[cbase + (size_t)(n + 1) * 1024 + tid * 4]);
            const size_t tokq = bt0 + (size_t)(n + 1) * CH;
            const uint32_t qdst = sb + ((n & 1) ? SI_Q1 : SI_Q0);
#pragma unroll
            for (int l = 0; l < 2; l++) {
                int i = tid + l * 256;
                int r = i >> 2, cc = i & 3;
                cpasync16(qdst + r * 64 + sw_chunk(r, cc) * 16,
                          qh + (tokq + r) * CC + h * DD + cc * 8);
            }
            cp_commit();
        }
        __syncthreads();   // protect KVHI overwrite + Q buffer rotation
    }
}

// ======================= launch =======================
extern "C" void kernel_launch(void* const* d_in, const int* in_sizes, int n_in,
                              void* d_out, int out_size)
{
    const float* x    = (const float*)d_in[0];
    const float* rel  = (const float*)d_in[1];
    const float* qkvw = (const float*)d_in[2];
    const float* qg   = (const float*)d_in[3];
    const float* kg   = (const float*)d_in[4];
    const float* pw   = (const float*)d_in[5];
    const float* pb   = (const float*)d_in[6];
    float* out = (float*)d_out;

    void* p_qkv = nullptr; cudaGetSymbolAddress(&p_qkv, g_qkv);
    void* p_A2  = nullptr; cudaGetSymbolAddress(&p_A2,  g_A2);
    void* p_W1h = nullptr; cudaGetSymbolAddress(&p_W1h, g_W1h);
    void* p_W2h = nullptr; cudaGetSymbolAddress(&p_W2h, g_W2h);
    void* p_qh  = nullptr; cudaGetSymbolAddress(&p_qh,  g_qh);

    cudaFuncSetAttribute(attn_chunk_hmma,
                         cudaFuncAttributeMaxDynamicSharedMemorySize, AT_SMEM);

    // 1) one fused conversion launch: act -> A2, W1 -> W1h, W2 -> W2h
    conv_all_kernel<<<CONV_GRID, 256>>>(x, rel, qkvw, pw,
        (__half*)p_A2, (__half*)p_W1h, (__half*)p_W2h);

    // 2) qkv = A @ W1h^T  (pure fp16 HMMA, K=256, BK=32) -> fp16 g_qkv
    gemm_f16_hmma<false, true><<<dim3(768/128, TT/128), 256>>>(
        (const __half*)p_A2, (const __half*)p_W1h, nullptr,
        p_qkv, 768);

    // 3) attention: intra (writes o fp16 into A2) + C_n, then fused scan+inter (RMW A2)
    attn_chunk_hmma<<<dim3(NC, HH, BB), 256, AT_SMEM>>>(
        qg, kg, (__half*)p_qh, (__half*)p_A2);
    scan_inter_hmma<<<dim3(HH, BB), 256>>>((const __half*)p_qh, (__half*)p_A2);

    // 4) out = O @ W2h^T + bias (fp32 out)
    gemm_f16_hmma<true, false><<<dim3(256/128, TT/128), 256>>>(
        (const __half*)p_A2, (const __half*)p_W2h, pb,
        out, 256);
}